// round 1
// baseline (speedup 1.0000x reference)
#include <cuda_runtime.h>
#include <cuda_bf16.h>
#include <cstdint>

// GATConv: x[N,128], W[64,128], a_src[4,16], a_dst[4,16], edge_index[2,E]
// out[N,64]
//
// Pipeline:
//  k0: zero out / e_max / e_sum
//  k1: GEMM h = x @ W^T          (smem-tiled fp32)
//  k2: per-(node,head) scores    score_src/score_dst
//  k3: edge pass 1: seg-max via atomicMax(int) with 0-floor
//  k4: edge pass 2: seg-sum of exp via red.global.add.v4.f32
//  k5: edge pass 3: gather h[src] * alpha, scatter-add to out[dst] (red.v4)

#define MAXN 100000
#define MAXE 1600000

__device__ float g_h[MAXN * 64];      // projected features
__device__ float g_ssrc[MAXN * 4];    // score_src per (node, head)
__device__ float g_sdst[MAXN * 4];    // score_dst per (node, head)
__device__ float g_emax[MAXN * 4];    // segment max (>= 0)
__device__ float g_esum[MAXN * 4];    // segment sum of exp

// -------------------------------------------------------------------------
// k0: zero scratch + output
__global__ void k_zero(float* __restrict__ out, int out_elems, int nh) {
    int i = blockIdx.x * blockDim.x + threadIdx.x;
    if (i < out_elems) out[i] = 0.0f;
    if (i < nh) { g_emax[i] = 0.0f; g_esum[i] = 0.0f; }
}

// -------------------------------------------------------------------------
// k1: GEMM. 256 threads / block, 32 nodes / block.
// Each thread: 2 nodes x 4 outputs. Xs: 32x128 f32 (16KB), Ws: 64x128 f32 (32KB).
__global__ __launch_bounds__(256) void k_gemm(const float* __restrict__ x,
                                              const float* __restrict__ W,
                                              int n) {
    __shared__ float4 Xs[32 * 32];   // [node][k4]
    __shared__ float4 Ws[64 * 32];   // [out][k4]
    const int tid = threadIdx.x;
    const int nbase = blockIdx.x * 32;

    const float4* W4 = (const float4*)W;
    const float4* x4 = (const float4*)x;
#pragma unroll
    for (int i = tid; i < 64 * 32; i += 256) Ws[i] = W4[i];
    for (int i = tid; i < 32 * 32; i += 256) {
        int node = nbase + (i >> 5);
        Xs[i] = (node < n) ? x4[(size_t)node * 32 + (i & 31)]
                           : make_float4(0.f, 0.f, 0.f, 0.f);
    }
    __syncthreads();

    const int og = (tid & 15) * 4;      // output group: 4 consecutive outputs
    const int ng = (tid >> 4) * 2;      // node group: 2 consecutive nodes
    float acc0[4] = {0.f, 0.f, 0.f, 0.f};
    float acc1[4] = {0.f, 0.f, 0.f, 0.f};

#pragma unroll 8
    for (int kk = 0; kk < 32; kk++) {
        float4 xv0 = Xs[ng * 32 + kk];
        float4 xv1 = Xs[(ng + 1) * 32 + kk];
#pragma unroll
        for (int j = 0; j < 4; j++) {
            float4 wv = Ws[(og + j) * 32 + kk];
            acc0[j] += xv0.x * wv.x + xv0.y * wv.y + xv0.z * wv.z + xv0.w * wv.w;
            acc1[j] += xv1.x * wv.x + xv1.y * wv.y + xv1.z * wv.z + xv1.w * wv.w;
        }
    }

    int n0 = nbase + ng;
    if (n0 < n)
        *(float4*)&g_h[(size_t)n0 * 64 + og] =
            make_float4(acc0[0], acc0[1], acc0[2], acc0[3]);
    if (n0 + 1 < n)
        *(float4*)&g_h[(size_t)(n0 + 1) * 64 + og] =
            make_float4(acc1[0], acc1[1], acc1[2], acc1[3]);
}

// -------------------------------------------------------------------------
// k2: per-(node,head) attention scores
__global__ void k_scores(const float* __restrict__ a_src,
                         const float* __restrict__ a_dst, int n) {
    int idx = blockIdx.x * blockDim.x + threadIdx.x;
    if (idx >= n * 4) return;
    int node = idx >> 2, head = idx & 3;
    const float4* hv = (const float4*)(g_h + (size_t)node * 64 + head * 16);
    const float4* as = (const float4*)(a_src + head * 16);
    const float4* ad = (const float4*)(a_dst + head * 16);
    float ds = 0.f, dd = 0.f;
#pragma unroll
    for (int i = 0; i < 4; i++) {
        float4 h4 = hv[i], s4 = as[i], d4 = ad[i];
        ds += h4.x * s4.x + h4.y * s4.y + h4.z * s4.z + h4.w * s4.w;
        dd += h4.x * d4.x + h4.y * d4.y + h4.z * d4.z + h4.w * d4.w;
    }
    g_ssrc[idx] = ds;
    g_sdst[idx] = dd;
}

// -------------------------------------------------------------------------
__device__ __forceinline__ void leaky4(float4 a, float4 b, float* t) {
    float v0 = a.x + b.x, v1 = a.y + b.y, v2 = a.z + b.z, v3 = a.w + b.w;
    t[0] = v0 > 0.f ? v0 : 0.2f * v0;
    t[1] = v1 > 0.f ? v1 : 0.2f * v1;
    t[2] = v2 > 0.f ? v2 : 0.2f * v2;
    t[3] = v3 > 0.f ? v3 : 0.2f * v3;
}

// k3: segment max over dst (floor 0 -> int atomicMax is valid, skip negatives)
__global__ void k_edge_max(const int* __restrict__ src,
                           const int* __restrict__ dst, int E) {
    int e = blockIdx.x * blockDim.x + threadIdx.x;
    if (e >= E) return;
    int s = src[e], d = dst[e];
    float4 es = ((const float4*)g_ssrc)[s];
    float4 ed = ((const float4*)g_sdst)[d];
    float t[4];
    leaky4(es, ed, t);
#pragma unroll
    for (int h = 0; h < 4; h++)
        if (t[h] > 0.f)
            atomicMax((int*)&g_emax[d * 4 + h], __float_as_int(t[h]));
}

// k4: segment sum of exp
__global__ void k_edge_sum(const int* __restrict__ src,
                           const int* __restrict__ dst, int E) {
    int e = blockIdx.x * blockDim.x + threadIdx.x;
    if (e >= E) return;
    int s = src[e], d = dst[e];
    float4 es = ((const float4*)g_ssrc)[s];
    float4 ed = ((const float4*)g_sdst)[d];
    float t[4];
    leaky4(es, ed, t);
    float4 m = ((const float4*)g_emax)[d];
    float e0 = __expf(t[0] - m.x), e1 = __expf(t[1] - m.y);
    float e2 = __expf(t[2] - m.z), e3 = __expf(t[3] - m.w);
    asm volatile("red.global.add.v4.f32 [%0], {%1,%2,%3,%4};" ::
                 "l"(&g_esum[d * 4]), "f"(e0), "f"(e1), "f"(e2), "f"(e3)
                 : "memory");
}

// k5: gather-scale-scatter. 16 lanes per edge, one float4 per lane.
__global__ __launch_bounds__(256) void k_edge_scatter(const int* __restrict__ src,
                                                      const int* __restrict__ dst,
                                                      float* __restrict__ out,
                                                      int E) {
    int g = blockIdx.x * blockDim.x + threadIdx.x;
    int e = g >> 4;
    if (e >= E) return;
    int l = g & 15;          // 0..15: which float4 of the 64-dim message
    int head = l >> 2;       // 4 float4s per head
    int s = src[e], d = dst[e];

    float ss = g_ssrc[s * 4 + head];
    float sd = g_sdst[d * 4 + head];
    float t = ss + sd;
    t = t > 0.f ? t : 0.2f * t;
    float ex = __expf(t - g_emax[d * 4 + head]);
    float su = g_esum[d * 4 + head];
    float alpha = ex / fmaxf(su, 1e-9f);

    float4 hv = ((const float4*)g_h)[(size_t)s * 16 + l];
    float m0 = hv.x * alpha, m1 = hv.y * alpha, m2 = hv.z * alpha,
          m3 = hv.w * alpha;
    asm volatile("red.global.add.v4.f32 [%0], {%1,%2,%3,%4};" ::
                 "l"(out + (size_t)d * 64 + l * 4), "f"(m0), "f"(m1), "f"(m2),
                 "f"(m3)
                 : "memory");
}

// -------------------------------------------------------------------------
extern "C" void kernel_launch(void* const* d_in, const int* in_sizes, int n_in,
                              void* d_out, int out_size) {
    const float* x = (const float*)d_in[0];
    const float* W = (const float*)d_in[1];
    const float* a_src = (const float*)d_in[2];
    const float* a_dst = (const float*)d_in[3];
    const int* edge = (const int*)d_in[4];

    int N = in_sizes[0] / 128;
    int E = in_sizes[4] / 2;
    if (N > MAXN) N = MAXN;
    if (E > MAXE) E = MAXE;
    const int* src = edge;
    const int* dst = edge + E;
    float* out = (float*)d_out;

    int zmax = out_size > N * 4 ? out_size : N * 4;
    k_zero<<<(zmax + 255) / 256, 256>>>(out, out_size, N * 4);
    k_gemm<<<(N + 31) / 32, 256>>>(x, W, N);
    k_scores<<<(N * 4 + 255) / 256, 256>>>(a_src, a_dst, N);
    k_edge_max<<<(E + 255) / 256, 256>>>(src, dst, E);
    k_edge_sum<<<(E + 255) / 256, 256>>>(src, dst, E);
    long long sthreads = (long long)E * 16;
    k_edge_scatter<<<(int)((sthreads + 255) / 256), 256>>>(src, dst, out, E);
}

// round 2
// speedup vs baseline: 1.1185x; 1.1185x over previous
#include <cuda_runtime.h>
#include <cuda_bf16.h>
#include <cstdint>

// GATConv via dst-sorted CSR, no float atomics.
//  k0: zero cnt
//  k1: GEMM h = x @ W^T
//  k2: per-(node,head) scores
//  k3: histogram of dst
//  k4a/b/c: exclusive scan of counts -> offsets, cursor
//  k5: scatter src ids into CSR order
//  k6: per-dst warp aggregate: expsum (pass1, stores unnormalized exp),
//      then gather h[src]*alpha accumulate in registers, single write.

#define MAXN 100000
#define MAXE 1600000
#define SCAN_BLK 1024
#define MAX_PARTS ((MAXN + SCAN_BLK - 1) / SCAN_BLK)   // 98

__device__ float g_h[MAXN * 64];        // projected features
__device__ float g_ssrc[MAXN * 4];      // score_src per (node, head)
__device__ float g_sdst[MAXN * 4];      // score_dst per (node, head)
__device__ float g_alpha[MAXE * 4];     // unnormalized exp per (edge-slot, head)
__device__ int   g_sorted_src[MAXE];    // src ids sorted by dst
__device__ int   g_cnt[MAXN];
__device__ int   g_off[MAXN];
__device__ int   g_cur[MAXN];
__device__ int   g_part[MAX_PARTS];

// -------------------------------------------------------------------------
__global__ void k_zero(int n) {
    int i = blockIdx.x * blockDim.x + threadIdx.x;
    if (i < n) g_cnt[i] = 0;
}

// -------------------------------------------------------------------------
// k1: GEMM. 256 threads / block, 32 nodes / block.
__global__ __launch_bounds__(256) void k_gemm(const float* __restrict__ x,
                                              const float* __restrict__ W,
                                              int n) {
    __shared__ float4 Xs[32 * 32];
    __shared__ float4 Ws[64 * 32];
    const int tid = threadIdx.x;
    const int nbase = blockIdx.x * 32;

    const float4* W4 = (const float4*)W;
    const float4* x4 = (const float4*)x;
#pragma unroll
    for (int i = tid; i < 64 * 32; i += 256) Ws[i] = W4[i];
    for (int i = tid; i < 32 * 32; i += 256) {
        int node = nbase + (i >> 5);
        Xs[i] = (node < n) ? x4[(size_t)node * 32 + (i & 31)]
                           : make_float4(0.f, 0.f, 0.f, 0.f);
    }
    __syncthreads();

    const int og = (tid & 15) * 4;
    const int ng = (tid >> 4) * 2;
    float acc0[4] = {0.f, 0.f, 0.f, 0.f};
    float acc1[4] = {0.f, 0.f, 0.f, 0.f};

#pragma unroll 8
    for (int kk = 0; kk < 32; kk++) {
        float4 xv0 = Xs[ng * 32 + kk];
        float4 xv1 = Xs[(ng + 1) * 32 + kk];
#pragma unroll
        for (int j = 0; j < 4; j++) {
            float4 wv = Ws[(og + j) * 32 + kk];
            acc0[j] += xv0.x * wv.x + xv0.y * wv.y + xv0.z * wv.z + xv0.w * wv.w;
            acc1[j] += xv1.x * wv.x + xv1.y * wv.y + xv1.z * wv.z + xv1.w * wv.w;
        }
    }

    int n0 = nbase + ng;
    if (n0 < n)
        *(float4*)&g_h[(size_t)n0 * 64 + og] =
            make_float4(acc0[0], acc0[1], acc0[2], acc0[3]);
    if (n0 + 1 < n)
        *(float4*)&g_h[(size_t)(n0 + 1) * 64 + og] =
            make_float4(acc1[0], acc1[1], acc1[2], acc1[3]);
}

// -------------------------------------------------------------------------
__global__ void k_scores(const float* __restrict__ a_src,
                         const float* __restrict__ a_dst, int n) {
    int idx = blockIdx.x * blockDim.x + threadIdx.x;
    if (idx >= n * 4) return;
    int node = idx >> 2, head = idx & 3;
    const float4* hv = (const float4*)(g_h + (size_t)node * 64 + head * 16);
    const float4* as = (const float4*)(a_src + head * 16);
    const float4* ad = (const float4*)(a_dst + head * 16);
    float ds = 0.f, dd = 0.f;
#pragma unroll
    for (int i = 0; i < 4; i++) {
        float4 h4 = hv[i], s4 = as[i], d4 = ad[i];
        ds += h4.x * s4.x + h4.y * s4.y + h4.z * s4.z + h4.w * s4.w;
        dd += h4.x * d4.x + h4.y * d4.y + h4.z * d4.z + h4.w * d4.w;
    }
    g_ssrc[idx] = ds;
    g_sdst[idx] = dd;
}

// -------------------------------------------------------------------------
__global__ void k_hist(const int* __restrict__ dst, int E) {
    int e = blockIdx.x * blockDim.x + threadIdx.x;
    if (e < E) atomicAdd(&g_cnt[dst[e]], 1);
}

// Block-level exclusive scan (Hillis-Steele in shared).
__global__ __launch_bounds__(SCAN_BLK) void k_scan1(int n) {
    __shared__ int s[SCAN_BLK];
    int t = threadIdx.x;
    int i = blockIdx.x * SCAN_BLK + t;
    int v = (i < n) ? g_cnt[i] : 0;
    s[t] = v;
    __syncthreads();
#pragma unroll
    for (int off = 1; off < SCAN_BLK; off <<= 1) {
        int x = (t >= off) ? s[t - off] : 0;
        __syncthreads();
        s[t] += x;
        __syncthreads();
    }
    if (i < n) g_off[i] = s[t] - v;                 // exclusive
    if (t == SCAN_BLK - 1) g_part[blockIdx.x] = s[t];
}

__global__ void k_scan2(int nparts) {
    __shared__ int s[MAX_PARTS];
    int t = threadIdx.x;
    if (t < nparts) s[t] = g_part[t];
    __syncthreads();
    if (t == 0) {
        int run = 0;
        for (int i = 0; i < nparts; i++) { int v = s[i]; s[i] = run; run += v; }
    }
    __syncthreads();
    if (t < nparts) g_part[t] = s[t];
}

__global__ void k_scan3(int n) {
    int i = blockIdx.x * blockDim.x + threadIdx.x;
    if (i < n) {
        int o = g_off[i] + g_part[i / SCAN_BLK];
        g_off[i] = o;
        g_cur[i] = o;
    }
}

// -------------------------------------------------------------------------
__global__ void k_fill(const int* __restrict__ src, const int* __restrict__ dst,
                       int E) {
    int e = blockIdx.x * blockDim.x + threadIdx.x;
    if (e >= E) return;
    int d = dst[e];
    int pos = atomicAdd(&g_cur[d], 1);
    g_sorted_src[pos] = src[e];
}

// -------------------------------------------------------------------------
// k6: one warp per dst node. Registers hold the 64-dim accumulator (float2/lane).
__global__ __launch_bounds__(256) void k_aggregate(float* __restrict__ out,
                                                   int n) {
    const int warp = threadIdx.x >> 5;
    const int lane = threadIdx.x & 31;
    const int d = blockIdx.x * 8 + warp;
    if (d >= n) return;

    const int start = g_off[d];
    const int cnt = g_cnt[d];
    const int head = lane >> 3;

    const float4 sd = ((const float4*)g_sdst)[d];   // broadcast load

    // pass 1: per-head sum of exp over this segment; store unnormalized exps
    float4 sum = make_float4(0.f, 0.f, 0.f, 0.f);
    for (int i = lane; i < cnt; i += 32) {
        int s = g_sorted_src[start + i];
        float4 ss = ((const float4*)g_ssrc)[s];
        float t0 = ss.x + sd.x, t1 = ss.y + sd.y;
        float t2 = ss.z + sd.z, t3 = ss.w + sd.w;
        t0 = t0 > 0.f ? t0 : 0.2f * t0;
        t1 = t1 > 0.f ? t1 : 0.2f * t1;
        t2 = t2 > 0.f ? t2 : 0.2f * t2;
        t3 = t3 > 0.f ? t3 : 0.2f * t3;
        float4 e4 = make_float4(__expf(t0), __expf(t1), __expf(t2), __expf(t3));
        ((float4*)g_alpha)[start + i] = e4;
        sum.x += e4.x; sum.y += e4.y; sum.z += e4.z; sum.w += e4.w;
    }
#pragma unroll
    for (int o = 16; o > 0; o >>= 1) {
        sum.x += __shfl_xor_sync(0xffffffffu, sum.x, o);
        sum.y += __shfl_xor_sync(0xffffffffu, sum.y, o);
        sum.z += __shfl_xor_sync(0xffffffffu, sum.z, o);
        sum.w += __shfl_xor_sync(0xffffffffu, sum.w, o);
    }
    float sum_h = (head < 2) ? (head == 0 ? sum.x : sum.y)
                             : (head == 2 ? sum.z : sum.w);
    const float myrs = 1.0f / fmaxf(sum_h, 1e-9f);

    // pass 2: gather h[src] * alpha, accumulate in registers
    float2 acc = make_float2(0.f, 0.f);
    for (int base = 0; base < cnt; base += 32) {
        int i = base + lane;
        int s_reg = (i < cnt) ? g_sorted_src[start + i] : 0;
        int lim = min(32, cnt - base);
#pragma unroll 4
        for (int j = 0; j < lim; j++) {
            int s = __shfl_sync(0xffffffffu, s_reg, j);
            float alpha = g_alpha[(size_t)(start + base + j) * 4 + head] * myrs;
            float2 h2 = ((const float2*)g_h)[(size_t)s * 32 + lane];
            acc.x += h2.x * alpha;
            acc.y += h2.y * alpha;
        }
    }
    ((float2*)out)[(size_t)d * 32 + lane] = acc;
}

// -------------------------------------------------------------------------
extern "C" void kernel_launch(void* const* d_in, const int* in_sizes, int n_in,
                              void* d_out, int out_size) {
    const float* x = (const float*)d_in[0];
    const float* W = (const float*)d_in[1];
    const float* a_src = (const float*)d_in[2];
    const float* a_dst = (const float*)d_in[3];
    const int* edge = (const int*)d_in[4];

    int N = in_sizes[0] / 128;
    int E = in_sizes[4] / 2;
    if (N > MAXN) N = MAXN;
    if (E > MAXE) E = MAXE;
    const int* src = edge;
    const int* dst = edge + E;
    float* out = (float*)d_out;

    int nparts = (N + SCAN_BLK - 1) / SCAN_BLK;

    k_zero<<<(N + 255) / 256, 256>>>(N);
    k_gemm<<<(N + 31) / 32, 256>>>(x, W, N);
    k_scores<<<(N * 4 + 255) / 256, 256>>>(a_src, a_dst, N);
    k_hist<<<(E + 255) / 256, 256>>>(dst, E);
    k_scan1<<<nparts, SCAN_BLK>>>(N);
    k_scan2<<<1, 128>>>(nparts);
    k_scan3<<<(N + 255) / 256, 256>>>(N);
    k_fill<<<(E + 255) / 256, 256>>>(src, dst, E);
    k_aggregate<<<(N + 7) / 8, 256>>>(out, N);
}

// round 3
// speedup vs baseline: 3.2040x; 2.8646x over previous
#include <cuda_runtime.h>
#include <cuda_bf16.h>
#include <cstdint>

// GATConv via dst-sorted CSR, no float atomics. R3: conflict-free GEMM.

#define MAXN 100000
#define MAXE 1600000
#define SCAN_BLK 1024
#define MAX_PARTS ((MAXN + SCAN_BLK - 1) / SCAN_BLK)

#define GN 128                    // nodes per gemm block
#define XS_STRIDE 129
#define WS_STRIDE 65
#define GEMM_SMEM ((GN * XS_STRIDE + 128 * WS_STRIDE) * 4)

__device__ float g_h[MAXN * 64];
__device__ float g_ssrc[MAXN * 4];
__device__ float g_sdst[MAXN * 4];
__device__ float g_alpha[MAXE * 4];
__device__ int   g_sorted_src[MAXE];
__device__ int   g_cnt[MAXN];
__device__ int   g_off[MAXN];
__device__ int   g_cur[MAXN];
__device__ int   g_part[MAX_PARTS];

// -------------------------------------------------------------------------
__global__ void k_zero(int n) {
    int i = blockIdx.x * blockDim.x + threadIdx.x;
    if (i < n) g_cnt[i] = 0;
}

// -------------------------------------------------------------------------
// GEMM: h = x @ W^T. 256 threads, 128 nodes/block, each thread 8 nodes x 4 outs.
// Xs[node][k] padded stride 129 (broadcast scalar reads, no column conflict).
// Ws_t[k][out] padded stride 65 (lane stride 4 words -> <=2-way).
__global__ __launch_bounds__(256) void k_gemm(const float* __restrict__ x,
                                              const float* __restrict__ W,
                                              int n) {
    extern __shared__ float smem[];
    float* Xs = smem;                       // [GN][129]
    float* Ws = smem + GN * XS_STRIDE;      // [128][65]
    const int tid = threadIdx.x;
    const int nbase = blockIdx.x * GN;

    // W transpose: [64][128] -> Ws[k][out]
    const float4* W4 = (const float4*)W;
#pragma unroll
    for (int i = tid; i < 64 * 32; i += 256) {
        int out = i >> 5, k4 = i & 31;
        float4 w = W4[i];
        Ws[(4 * k4 + 0) * WS_STRIDE + out] = w.x;
        Ws[(4 * k4 + 1) * WS_STRIDE + out] = w.y;
        Ws[(4 * k4 + 2) * WS_STRIDE + out] = w.z;
        Ws[(4 * k4 + 3) * WS_STRIDE + out] = w.w;
    }
    // X tile: [GN][128]
    const float4* x4 = (const float4*)x;
#pragma unroll
    for (int i = tid; i < GN * 32; i += 256) {
        int r = i >> 5, k4 = i & 31;
        int node = nbase + r;
        float4 v = (node < n) ? x4[(size_t)node * 32 + k4]
                              : make_float4(0.f, 0.f, 0.f, 0.f);
        Xs[r * XS_STRIDE + 4 * k4 + 0] = v.x;
        Xs[r * XS_STRIDE + 4 * k4 + 1] = v.y;
        Xs[r * XS_STRIDE + 4 * k4 + 2] = v.z;
        Xs[r * XS_STRIDE + 4 * k4 + 3] = v.w;
    }
    __syncthreads();

    const int og = (tid & 15) * 4;       // 4 consecutive outputs
    const int ng = (tid >> 4) * 8;       // 8 consecutive nodes
    float acc[8][4];
#pragma unroll
    for (int i = 0; i < 8; i++)
#pragma unroll
        for (int j = 0; j < 4; j++) acc[i][j] = 0.f;

#pragma unroll 4
    for (int k = 0; k < 128; k++) {
        const float* wr = Ws + k * WS_STRIDE + og;
        float w0 = wr[0], w1 = wr[1], w2 = wr[2], w3 = wr[3];
#pragma unroll
        for (int i = 0; i < 8; i++) {
            float xv = Xs[(ng + i) * XS_STRIDE + k];
            acc[i][0] += xv * w0;
            acc[i][1] += xv * w1;
            acc[i][2] += xv * w2;
            acc[i][3] += xv * w3;
        }
    }

#pragma unroll
    for (int i = 0; i < 8; i++) {
        int node = nbase + ng + i;
        if (node < n)
            *(float4*)&g_h[(size_t)node * 64 + og] =
                make_float4(acc[i][0], acc[i][1], acc[i][2], acc[i][3]);
    }
}

// -------------------------------------------------------------------------
__global__ void k_scores(const float* __restrict__ a_src,
                         const float* __restrict__ a_dst, int n) {
    int idx = blockIdx.x * blockDim.x + threadIdx.x;
    if (idx >= n * 4) return;
    int node = idx >> 2, head = idx & 3;
    const float4* hv = (const float4*)(g_h + (size_t)node * 64 + head * 16);
    const float4* as = (const float4*)(a_src + head * 16);
    const float4* ad = (const float4*)(a_dst + head * 16);
    float ds = 0.f, dd = 0.f;
#pragma unroll
    for (int i = 0; i < 4; i++) {
        float4 h4 = hv[i], s4 = as[i], d4 = ad[i];
        ds += h4.x * s4.x + h4.y * s4.y + h4.z * s4.z + h4.w * s4.w;
        dd += h4.x * d4.x + h4.y * d4.y + h4.z * d4.z + h4.w * d4.w;
    }
    g_ssrc[idx] = ds;
    g_sdst[idx] = dd;
}

// -------------------------------------------------------------------------
__global__ void k_hist(const int* __restrict__ dst, int E) {
    int e = blockIdx.x * blockDim.x + threadIdx.x;
    if (e < E) atomicAdd(&g_cnt[dst[e]], 1);
}

__global__ __launch_bounds__(SCAN_BLK) void k_scan1(int n) {
    __shared__ int s[SCAN_BLK];
    int t = threadIdx.x;
    int i = blockIdx.x * SCAN_BLK + t;
    int v = (i < n) ? g_cnt[i] : 0;
    s[t] = v;
    __syncthreads();
#pragma unroll
    for (int off = 1; off < SCAN_BLK; off <<= 1) {
        int x = (t >= off) ? s[t - off] : 0;
        __syncthreads();
        s[t] += x;
        __syncthreads();
    }
    if (i < n) g_off[i] = s[t] - v;
    if (t == SCAN_BLK - 1) g_part[blockIdx.x] = s[t];
}

__global__ void k_scan2(int nparts) {
    __shared__ int s[MAX_PARTS];
    int t = threadIdx.x;
    if (t < nparts) s[t] = g_part[t];
    __syncthreads();
    if (t == 0) {
        int run = 0;
        for (int i = 0; i < nparts; i++) { int v = s[i]; s[i] = run; run += v; }
    }
    __syncthreads();
    if (t < nparts) g_part[t] = s[t];
}

__global__ void k_scan3(int n) {
    int i = blockIdx.x * blockDim.x + threadIdx.x;
    if (i < n) {
        int o = g_off[i] + g_part[i / SCAN_BLK];
        g_off[i] = o;
        g_cur[i] = o;
    }
}

// -------------------------------------------------------------------------
__global__ void k_fill(const int* __restrict__ src, const int* __restrict__ dst,
                       int E) {
    int e = blockIdx.x * blockDim.x + threadIdx.x;
    if (e >= E) return;
    int d = dst[e];
    int pos = atomicAdd(&g_cur[d], 1);
    g_sorted_src[pos] = src[e];
}

// -------------------------------------------------------------------------
__global__ __launch_bounds__(256) void k_aggregate(float* __restrict__ out,
                                                   int n) {
    const int warp = threadIdx.x >> 5;
    const int lane = threadIdx.x & 31;
    const int d = blockIdx.x * 8 + warp;
    if (d >= n) return;

    const int start = g_off[d];
    const int cnt = g_cnt[d];
    const int head = lane >> 3;

    const float4 sd = ((const float4*)g_sdst)[d];

    float4 sum = make_float4(0.f, 0.f, 0.f, 0.f);
    for (int i = lane; i < cnt; i += 32) {
        int s = g_sorted_src[start + i];
        float4 ss = ((const float4*)g_ssrc)[s];
        float t0 = ss.x + sd.x, t1 = ss.y + sd.y;
        float t2 = ss.z + sd.z, t3 = ss.w + sd.w;
        t0 = t0 > 0.f ? t0 : 0.2f * t0;
        t1 = t1 > 0.f ? t1 : 0.2f * t1;
        t2 = t2 > 0.f ? t2 : 0.2f * t2;
        t3 = t3 > 0.f ? t3 : 0.2f * t3;
        float4 e4 = make_float4(__expf(t0), __expf(t1), __expf(t2), __expf(t3));
        ((float4*)g_alpha)[start + i] = e4;
        sum.x += e4.x; sum.y += e4.y; sum.z += e4.z; sum.w += e4.w;
    }
#pragma unroll
    for (int o = 16; o > 0; o >>= 1) {
        sum.x += __shfl_xor_sync(0xffffffffu, sum.x, o);
        sum.y += __shfl_xor_sync(0xffffffffu, sum.y, o);
        sum.z += __shfl_xor_sync(0xffffffffu, sum.z, o);
        sum.w += __shfl_xor_sync(0xffffffffu, sum.w, o);
    }
    float sum_h = (head < 2) ? (head == 0 ? sum.x : sum.y)
                             : (head == 2 ? sum.z : sum.w);
    const float myrs = 1.0f / fmaxf(sum_h, 1e-9f);

    float2 acc = make_float2(0.f, 0.f);
    for (int base = 0; base < cnt; base += 32) {
        int i = base + lane;
        int s_reg = (i < cnt) ? g_sorted_src[start + i] : 0;
        int lim = min(32, cnt - base);
#pragma unroll 4
        for (int j = 0; j < lim; j++) {
            int s = __shfl_sync(0xffffffffu, s_reg, j);
            float alpha = g_alpha[(size_t)(start + base + j) * 4 + head] * myrs;
            float2 h2 = ((const float2*)g_h)[(size_t)s * 32 + lane];
            acc.x += h2.x * alpha;
            acc.y += h2.y * alpha;
        }
    }
    ((float2*)out)[(size_t)d * 32 + lane] = acc;
}

// -------------------------------------------------------------------------
extern "C" void kernel_launch(void* const* d_in, const int* in_sizes, int n_in,
                              void* d_out, int out_size) {
    const float* x = (const float*)d_in[0];
    const float* W = (const float*)d_in[1];
    const float* a_src = (const float*)d_in[2];
    const float* a_dst = (const float*)d_in[3];
    const int* edge = (const int*)d_in[4];

    int N = in_sizes[0] / 128;
    int E = in_sizes[4] / 2;
    if (N > MAXN) N = MAXN;
    if (E > MAXE) E = MAXE;
    const int* src = edge;
    const int* dst = edge + E;
    float* out = (float*)d_out;

    int nparts = (N + SCAN_BLK - 1) / SCAN_BLK;

    cudaFuncSetAttribute(k_gemm, cudaFuncAttributeMaxDynamicSharedMemorySize,
                         GEMM_SMEM);

    k_zero<<<(N + 255) / 256, 256>>>(N);
    k_gemm<<<(N + GN - 1) / GN, 256, GEMM_SMEM>>>(x, W, N);
    k_scores<<<(N * 4 + 255) / 256, 256>>>(a_src, a_dst, N);
    k_hist<<<(E + 255) / 256, 256>>>(dst, E);
    k_scan1<<<nparts, SCAN_BLK>>>(N);
    k_scan2<<<1, 128>>>(nparts);
    k_scan3<<<(N + 255) / 256, 256>>>(N);
    k_fill<<<(E + 255) / 256, 256>>>(src, dst, E);
    k_aggregate<<<(N + 7) / 8, 256>>>(out, N);
}